// round 13
// baseline (speedup 1.0000x reference)
#include <cuda_runtime.h>
#include <cuda_bf16.h>

// EdgeIndexGenerator — image-replication, GRP=4 image-groups, float32 [2,E].
// R12 -> R13: double thread-level parallelism (GRP 8->4, 222K threads,
// TPB 512) to shrink the exposed store-latency phase; occ 32% -> ~70%.
//
// Interface (validated R6-R12): out = float32, E = out_size/2,
// out[0:E]=src, out[E:2E]=dst. Node ids < 2^24, exact in fp32.
//
// FAST PATH (H=W=56 baked): thread (pair k/2, group g) decodes edge slots
// (k, k+1) of image 0 once, then stores float2 {v,v}+b*3136 for its GRP
// images. Coalesced STG.64 (k even, E even -> 8B aligned). Tail pair by
// (pair 0, last group).
//
// GENERIC FALLBACK (any other E): setup + per-edge magic-division kernel.

// ----------------------- fast path (H = W = 56) -----------------------------
static constexpr int Hc = 56, Wc = 56, HWc = Hc * Wc;         // 3136
static constexpr int BORDER   = 7 * Wc - 4;                   // 388
static constexpr int INTERIOR = 9 * Wc - 4;                   // 500
static constexpr int EIMG = 2 * BORDER + (Hc - 2) * INTERIOR; // 27776
static constexpr int NPAIRS = EIMG / 2;                       // 13888
static constexpr int GRP = 4;                                 // images/thread
static constexpr int TPB = 512;

// Decode edge slot k (0 <= k < EIMG) of image 0 -> (src, dst) as floats.
// Formulas validated R10-R12 (rel_err 0).
__device__ __forceinline__ void decode_edge0(int k, float* vs, float* vd)
{
    int y, inr;
    if (k < BORDER) { y = 0; inr = k; }
    else {
        const int r2 = k - BORDER;
        const int q  = (int)((unsigned)r2 / (unsigned)INTERIOR); // const magic
        y   = 1 + q;                          // q==H-2 -> y==H-1 (len<INTERIOR)
        inr = r2 - q * INTERIOR;
    }

    const bool topbot = (y == 0) | (y == Hc - 1);
    const unsigned u  = (unsigned)(inr + 2);
    const int x   = topbot ? (int)(u / 7u) : (int)(u / 9u);     // const magics
    const int s   = topbot ? 7 : 9;
    const int rem = (int)u - x * s;
    const int slot = rem - ((x == 0) ? 2 : 0);

    const int i = y * Wc + x;
    const float fi = (float)i;

    float a = fi, c = fi;                      // slot 0: self edge
    if (slot > 0) {
        const int j  = slot - 1;
        const int pi = j >> 1;
        const int q2 = j & 1;
        int f = pi + (x == 0);
        f += (x == Wc - 1 && f >= 1);
        f += (y == 0      && f >= 2);
        const int delta = ((f & 1) ? 1 : -1) * ((f >= 2) ? Wc : 1);
        const float o = fi + (float)delta;
        a = q2 ? o : fi;
        c = q2 ? fi : o;
    }
    *vs = a; *vd = c;
}

__global__ __launch_bounds__(TPB) void fast_kernel(float* __restrict__ out,
                                                   int E, int Nimg,
                                                   int ngroups, int has_tail)
{
    const int idx = blockIdx.x * TPB + threadIdx.x;
    const int total = NPAIRS * ngroups;
    if (idx >= total) return;

    // Consecutive threads -> consecutive pairs (coalesced within a group).
    const int g    = idx / NPAIRS;             // image group (const divisor)
    const int pair = idx - g * NPAIRS;
    const int k    = pair * 2;

    const int b0 = g * GRP;
    const int nb = min(Nimg - b0, GRP);        // == GRP when Nimg % GRP == 0

    float s0, d0, s1, d1;
    decode_edge0(k,     &s0, &d0);
    decode_edge0(k + 1, &s1, &d1);             // k+1 < EIMG (EIMG even)

    const float fbase = (float)(b0 * HWc);     // exact: < 2^24
    float2 sv = make_float2(s0 + fbase, s1 + fbase);
    float2 dv = make_float2(d0 + fbase, d1 + fbase);

    float* __restrict__ ps = out + b0 * EIMG + k;        // 8B aligned
    float* __restrict__ pd = out + E + b0 * EIMG + k;    // 8B aligned (E even)

    #pragma unroll
    for (int b = 0; b < GRP; ++b) {
        if (b < nb) {                          // predicated, uniform per warp
            *(float2*)ps = sv;
            *(float2*)pd = dv;
        }
        sv.x += (float)HWc; sv.y += (float)HWc;
        dv.x += (float)HWc; dv.y += (float)HWc;
        ps += EIMG; pd += EIMG;
    }

    if (pair == 0 && g == ngroups - 1 && has_tail) {
        // Trailing symmetric pair (reference loop-leak): last node pairs
        // with node (0,0) of the last image.
        const int body   = Nimg * EIMG;
        const float il   = (float)(Nimg * HWc - 1);
        const float sidx = (float)((Nimg - 1) * HWc);
        out[body]         = il;   out[body + 1]     = sidx;
        out[E + body]     = sidx; out[E + body + 1] = il;
    }
}

// --------------------------- generic fallback -------------------------------
struct EdgeParams {
    int H, W, HW;
    int border, interior, Eimg, body;
    unsigned ME; int pE;
    unsigned MI; int pI;
    int i_last, sidx;
};
__device__ EdgeParams g_p;

__device__ __forceinline__ int decode_dim(const int* p) {
    if (p == nullptr) return 56;
    int v = *p;
    if (v >= 1 && v <= 65536) return v;
    float f = __int_as_float(v);
    if (f >= 1.0f && f <= 65536.0f && f == floorf(f)) return (int)f;
    return 56;
}

__device__ void make_magic(unsigned d, unsigned nmax, unsigned* M, int* p) {
    int pp = 32;
    for (;;) {
        unsigned long long Mv = ((1ULL << pp) + d - 1) / d;
        unsigned long long r  = Mv * d - (1ULL << pp);
        if (r * (unsigned long long)nmax < (1ULL << pp) && Mv <= 0xFFFFFFFFULL) {
            *M = (unsigned)Mv; *p = pp; return;
        }
        if (++pp > 60) { *M = 1; *p = 0; return; }
    }
}

__global__ void setup_kernel(const int* hptr, const int* wptr, int E) {
    const int H = decode_dim(hptr);
    const int W = decode_dim(wptr);
    EdgeParams P;
    P.H = H; P.W = W; P.HW = H * W;
    P.border   = 7 * W - 4;
    P.interior = 9 * W - 4;
    P.Eimg     = 2 * P.border + (H - 2) * P.interior;
    const int Nimg = E / P.Eimg;
    P.body   = Nimg * P.Eimg;
    P.i_last = Nimg * P.HW - 1;
    P.sidx   = (Nimg - 1) * P.HW;
    make_magic((unsigned)P.Eimg,     (unsigned)(E > 0 ? E - 1 : 0), &P.ME, &P.pE);
    make_magic((unsigned)P.interior, (unsigned)(P.Eimg - 1),        &P.MI, &P.pI);
    g_p = P;
}

__global__ __launch_bounds__(256) void generic_kernel(float* __restrict__ out,
                                                      int E)
{
    const int e = blockIdx.x * 256 + threadIdx.x;
    if (e >= E) return;
    const EdgeParams P = g_p;

    if (e >= P.body) {
        const bool first = (e == P.body);
        out[e]     = (float)(first ? P.i_last : P.sidx);
        out[E + e] = (float)(first ? P.sidx   : P.i_last);
        return;
    }

    const unsigned b = (unsigned)(((unsigned long long)(unsigned)e * P.ME) >> P.pE);
    const int r = e - (int)b * P.Eimg;

    int y, inr;
    if (r < P.border) { y = 0; inr = r; }
    else {
        const int r2 = r - P.border;
        const unsigned q = (unsigned)(((unsigned long long)(unsigned)r2 * P.MI) >> P.pI);
        if ((int)q < P.H - 2) { y = 1 + (int)q; inr = r2 - (int)q * P.interior; }
        else                  { y = P.H - 1;    inr = r2 - (P.H - 2) * P.interior; }
    }

    const int vy = (y > 0) + (y < P.H - 1);
    const int s  = 5 + 2 * vy;
    const unsigned Ms = (vy == 2) ? 7282u : ((vy == 1) ? 9363u : 13108u);
    const int x = (int)(((unsigned)(inr + 2) * Ms) >> 16);
    const int slot = inr - (x ? (x * s - 2) : 0);

    const int i = (int)b * P.HW + y * P.W + x;

    int src = i, dst = i;
    if (slot > 0) {
        int j = slot - 1;
        int other;
        if (x > 0)       { if (j < 2) { other = i - 1;   goto emit; } j -= 2; }
        if (x < P.W - 1) { if (j < 2) { other = i + 1;   goto emit; } j -= 2; }
        if (y > 0)       { if (j < 2) { other = i - P.W; goto emit; } j -= 2; }
        other = i + P.W;
emit:
        src = (j == 0) ? i : other;
        dst = (j == 0) ? other : i;
    }

    out[e]     = (float)src;
    out[E + e] = (float)dst;
}

// ------------------------------- launch --------------------------------------
extern "C" void kernel_launch(void* const* d_in, const int* in_sizes, int n_in,
                              void* d_out, int out_size)
{
    float* out = (float*)d_out;
    const int E = out_size / 2;

    // Fast path: E consistent with H=W=56 (the problem's deterministic shape).
    const int Nimg = E / EIMG;
    const int rem  = E - Nimg * EIMG;
    if (Nimg >= 1 && (rem == 0 || rem == 2)) {
        const int ngroups = (Nimg + GRP - 1) / GRP;
        const int total   = NPAIRS * ngroups;
        const int blocks  = (total + TPB - 1) / TPB;
        fast_kernel<<<blocks, TPB>>>(out, E, Nimg, ngroups, rem == 2);
        return;
    }

    // Generic fallback: read H/W from device scalars.
    const int* hptr = (n_in >= 3) ? (const int*)d_in[1] : nullptr;
    const int* wptr = (n_in >= 3) ? (const int*)d_in[2] : nullptr;
    setup_kernel<<<1, 1>>>(hptr, wptr, E);
    generic_kernel<<<(E + 255) / 256, 256>>>(out, E);
}

// round 14
// speedup vs baseline: 1.3478x; 1.3478x over previous
#include <cuda_runtime.h>
#include <cuda_bf16.h>

// EdgeIndexGenerator — image-replication, GRP=8 (R12 config) + batched stores.
// R13 regressed (GRP=4 doubled decode work); revert to GRP=8/TPB=256 and
// instead: (a) 2D grid kills the idx/NPAIRS division, (b) uniform nb==GRP
// fast branch with 16 independent back-to-back STG.64 (no loop-carried
// control dep) maximizes store MLP per thread.
//
// Interface (validated R6-R13): out = float32, E = out_size/2,
// out[0:E]=src, out[E:2E]=dst. Node ids < 2^24, exact in fp32.
//
// FAST PATH (H=W=56 baked): thread (pair, group g) decodes edge slots
// (k, k+1) of image 0 once, then stores float2 {v,v}+b*3136 for its GRP
// images. Coalesced STG.64 (k even, E even -> 8B aligned). Tail pair by
// (pair 0, last group).
//
// GENERIC FALLBACK (any other E): setup + per-edge magic-division kernel.

// ----------------------- fast path (H = W = 56) -----------------------------
static constexpr int Hc = 56, Wc = 56, HWc = Hc * Wc;         // 3136
static constexpr int BORDER   = 7 * Wc - 4;                   // 388
static constexpr int INTERIOR = 9 * Wc - 4;                   // 500
static constexpr int EIMG = 2 * BORDER + (Hc - 2) * INTERIOR; // 27776
static constexpr int NPAIRS = EIMG / 2;                       // 13888
static constexpr int GRP = 8;                                 // images/thread
static constexpr int TPB = 256;

// Decode edge slot k (0 <= k < EIMG) of image 0 -> (src, dst) as floats.
// Formulas validated R10-R13 (rel_err 0).
__device__ __forceinline__ void decode_edge0(int k, float* vs, float* vd)
{
    int y, inr;
    if (k < BORDER) { y = 0; inr = k; }
    else {
        const int r2 = k - BORDER;
        const int q  = (int)((unsigned)r2 / (unsigned)INTERIOR); // const magic
        y   = 1 + q;                          // q==H-2 -> y==H-1 (len<INTERIOR)
        inr = r2 - q * INTERIOR;
    }

    const bool topbot = (y == 0) | (y == Hc - 1);
    const unsigned u  = (unsigned)(inr + 2);
    const int x   = topbot ? (int)(u / 7u) : (int)(u / 9u);     // const magics
    const int s   = topbot ? 7 : 9;
    const int rem = (int)u - x * s;
    const int slot = rem - ((x == 0) ? 2 : 0);

    const int i = y * Wc + x;
    const float fi = (float)i;

    float a = fi, c = fi;                      // slot 0: self edge
    if (slot > 0) {
        const int j  = slot - 1;
        const int pi = j >> 1;
        const int q2 = j & 1;
        int f = pi + (x == 0);
        f += (x == Wc - 1 && f >= 1);
        f += (y == 0      && f >= 2);
        const int delta = ((f & 1) ? 1 : -1) * ((f >= 2) ? Wc : 1);
        const float o = fi + (float)delta;
        a = q2 ? o : fi;
        c = q2 ? fi : o;
    }
    *vs = a; *vd = c;
}

__global__ __launch_bounds__(TPB) void fast_kernel(float* __restrict__ out,
                                                   int E, int Nimg,
                                                   int has_tail)
{
    const int pair = blockIdx.x * TPB + threadIdx.x;
    if (pair >= NPAIRS) return;
    const int g = blockIdx.y;                  // image group
    const int k = pair * 2;

    const int b0 = g * GRP;
    const int nb = min(Nimg - b0, GRP);        // == GRP when Nimg % GRP == 0

    float s0, d0, s1, d1;
    decode_edge0(k,     &s0, &d0);
    decode_edge0(k + 1, &s1, &d1);             // k+1 < EIMG (EIMG even)

    const float fbase = (float)(b0 * HWc);     // exact: < 2^24
    const float fs0 = s0 + fbase, fs1 = s1 + fbase;
    const float fd0 = d0 + fbase, fd1 = d1 + fbase;

    float* __restrict__ ps = out + b0 * EIMG + k;        // 8B aligned
    float* __restrict__ pd = out + E + b0 * EIMG + k;    // 8B aligned (E even)

    if (nb == GRP) {
        // Uniform fast branch: 16 independent STG.64 back-to-back.
        #pragma unroll
        for (int b = 0; b < GRP; ++b) {
            const float o = (float)(b * HWc);
            *(float2*)(ps + b * EIMG) = make_float2(fs0 + o, fs1 + o);
            *(float2*)(pd + b * EIMG) = make_float2(fd0 + o, fd1 + o);
        }
    } else {
        #pragma unroll
        for (int b = 0; b < GRP; ++b) {
            if (b < nb) {
                const float o = (float)(b * HWc);
                *(float2*)(ps + b * EIMG) = make_float2(fs0 + o, fs1 + o);
                *(float2*)(pd + b * EIMG) = make_float2(fd0 + o, fd1 + o);
            }
        }
    }

    if (pair == 0 && b0 + nb == Nimg && has_tail) {
        // Trailing symmetric pair (reference loop-leak): last node pairs
        // with node (0,0) of the last image.
        const int body   = Nimg * EIMG;
        const float il   = (float)(Nimg * HWc - 1);
        const float sidx = (float)((Nimg - 1) * HWc);
        out[body]         = il;   out[body + 1]     = sidx;
        out[E + body]     = sidx; out[E + body + 1] = il;
    }
}

// --------------------------- generic fallback -------------------------------
struct EdgeParams {
    int H, W, HW;
    int border, interior, Eimg, body;
    unsigned ME; int pE;
    unsigned MI; int pI;
    int i_last, sidx;
};
__device__ EdgeParams g_p;

__device__ __forceinline__ int decode_dim(const int* p) {
    if (p == nullptr) return 56;
    int v = *p;
    if (v >= 1 && v <= 65536) return v;
    float f = __int_as_float(v);
    if (f >= 1.0f && f <= 65536.0f && f == floorf(f)) return (int)f;
    return 56;
}

__device__ void make_magic(unsigned d, unsigned nmax, unsigned* M, int* p) {
    int pp = 32;
    for (;;) {
        unsigned long long Mv = ((1ULL << pp) + d - 1) / d;
        unsigned long long r  = Mv * d - (1ULL << pp);
        if (r * (unsigned long long)nmax < (1ULL << pp) && Mv <= 0xFFFFFFFFULL) {
            *M = (unsigned)Mv; *p = pp; return;
        }
        if (++pp > 60) { *M = 1; *p = 0; return; }
    }
}

__global__ void setup_kernel(const int* hptr, const int* wptr, int E) {
    const int H = decode_dim(hptr);
    const int W = decode_dim(wptr);
    EdgeParams P;
    P.H = H; P.W = W; P.HW = H * W;
    P.border   = 7 * W - 4;
    P.interior = 9 * W - 4;
    P.Eimg     = 2 * P.border + (H - 2) * P.interior;
    const int Nimg = E / P.Eimg;
    P.body   = Nimg * P.Eimg;
    P.i_last = Nimg * P.HW - 1;
    P.sidx   = (Nimg - 1) * P.HW;
    make_magic((unsigned)P.Eimg,     (unsigned)(E > 0 ? E - 1 : 0), &P.ME, &P.pE);
    make_magic((unsigned)P.interior, (unsigned)(P.Eimg - 1),        &P.MI, &P.pI);
    g_p = P;
}

__global__ __launch_bounds__(256) void generic_kernel(float* __restrict__ out,
                                                      int E)
{
    const int e = blockIdx.x * 256 + threadIdx.x;
    if (e >= E) return;
    const EdgeParams P = g_p;

    if (e >= P.body) {
        const bool first = (e == P.body);
        out[e]     = (float)(first ? P.i_last : P.sidx);
        out[E + e] = (float)(first ? P.sidx   : P.i_last);
        return;
    }

    const unsigned b = (unsigned)(((unsigned long long)(unsigned)e * P.ME) >> P.pE);
    const int r = e - (int)b * P.Eimg;

    int y, inr;
    if (r < P.border) { y = 0; inr = r; }
    else {
        const int r2 = r - P.border;
        const unsigned q = (unsigned)(((unsigned long long)(unsigned)r2 * P.MI) >> P.pI);
        if ((int)q < P.H - 2) { y = 1 + (int)q; inr = r2 - (int)q * P.interior; }
        else                  { y = P.H - 1;    inr = r2 - (P.H - 2) * P.interior; }
    }

    const int vy = (y > 0) + (y < P.H - 1);
    const int s  = 5 + 2 * vy;
    const unsigned Ms = (vy == 2) ? 7282u : ((vy == 1) ? 9363u : 13108u);
    const int x = (int)(((unsigned)(inr + 2) * Ms) >> 16);
    const int slot = inr - (x ? (x * s - 2) : 0);

    const int i = (int)b * P.HW + y * P.W + x;

    int src = i, dst = i;
    if (slot > 0) {
        int j = slot - 1;
        int other;
        if (x > 0)       { if (j < 2) { other = i - 1;   goto emit; } j -= 2; }
        if (x < P.W - 1) { if (j < 2) { other = i + 1;   goto emit; } j -= 2; }
        if (y > 0)       { if (j < 2) { other = i - P.W; goto emit; } j -= 2; }
        other = i + P.W;
emit:
        src = (j == 0) ? i : other;
        dst = (j == 0) ? other : i;
    }

    out[e]     = (float)src;
    out[E + e] = (float)dst;
}

// ------------------------------- launch --------------------------------------
extern "C" void kernel_launch(void* const* d_in, const int* in_sizes, int n_in,
                              void* d_out, int out_size)
{
    float* out = (float*)d_out;
    const int E = out_size / 2;

    // Fast path: E consistent with H=W=56 (the problem's deterministic shape).
    const int Nimg = E / EIMG;
    const int rem  = E - Nimg * EIMG;
    if (Nimg >= 1 && (rem == 0 || rem == 2)) {
        const int ngroups = (Nimg + GRP - 1) / GRP;
        dim3 grid((NPAIRS + TPB - 1) / TPB, ngroups);
        fast_kernel<<<grid, TPB>>>(out, E, Nimg, rem == 2);
        return;
    }

    // Generic fallback: read H/W from device scalars.
    const int* hptr = (n_in >= 3) ? (const int*)d_in[1] : nullptr;
    const int* wptr = (n_in >= 3) ? (const int*)d_in[2] : nullptr;
    setup_kernel<<<1, 1>>>(hptr, wptr, E);
    generic_kernel<<<(E + 255) / 256, 256>>>(out, E);
}